// round 16
// baseline (speedup 1.0000x reference)
#include <cuda_runtime.h>
#include <math.h>

// ---------------------------------------------------------------------------
// EqAMPBC: M=41, RHO=1.0, Nmodes=2, B=131072
// PLANAR complex output (R14/R15): out[0..2B)=re (B,2), out[2B..4B)=im (B,2).
// in_sizes / out_size are BYTE counts.
// R16: 2 threads per batch (m>0 / m<0 halves) -> 16 warps/SM instead of 8.
// ---------------------------------------------------------------------------

#define MM    41
#define PP    20
#define HDIM  260
#define NB    64         // batches per block
#define TPB   128        // 2 threads per batch

// Compile-time tables in PART-MAJOR order: part0 = m=+1..+20, part1 = m=-1..-20.
// origh[] maps my pair index -> reference-order fwm weight index.
struct PTab {
    short grp_m[40];
    short gpair[41];
    short pgs[3];
    short npair[HDIM];
    short origh[HDIM];
    int   cnt;
    constexpr PTab() : grp_m(), gpair(), pgs(), npair(), origh(), cnt(0) {
        int ref_start[41] = {};
        {
            int idx = 0;
            for (int mi = 0; mi < 41; ++mi) {
                ref_start[mi] = idx;
                const int m = mi - 20;
                for (int n = -20; n <= 20; ++n) {
                    int a = m * n; if (a < 0) a = -a;
                    int s = m + n; if (s < 0) s = -s;
                    if (m != 0 && n != 0 && a <= 20 && s <= 20) ++idx;
                }
            }
        }
        int g = 0, pr = 0;
        pgs[0] = 0;
        gpair[0] = 0;
        for (int part = 0; part < 2; ++part) {
            for (int k = 1; k <= 20; ++k) {
                const int m = part ? -k : k;
                grp_m[g] = (short)m;
                int pos = 0;
                for (int n = -20; n <= 20; ++n) {
                    int a = m * n; if (a < 0) a = -a;
                    int s = m + n; if (s < 0) s = -s;
                    if (n != 0 && a <= 20 && s <= 20) {
                        npair[pr] = (short)n;
                        origh[pr] = (short)(ref_start[m + 20] + pos);
                        ++pr; ++pos;
                    }
                }
                ++g;
                gpair[g] = (short)pr;
            }
            pgs[part + 1] = (short)g;
        }
        cnt = pr;
    }
};
static_assert(PTab().cnt == HDIM, "pair count mismatch");
static_assert(PTab().gpair[20] == 130, "half split mismatch");

// One part's FWM + quadratic terms. Fully unrolled; all smem offsets immediate.
// acc: E0r,E0i,E1r,E1i, ph0,ph1, c0r,c0i
template<int PART>
__device__ __forceinline__ void fwm_part(const float4* __restrict__ xb,
                                         const float4* __restrict__ shw,
                                         const float2* __restrict__ shw12,
                                         float acc[8])
{
    constexpr PTab PT{};
#pragma unroll
    for (int g = PT.pgs[PART]; g < PT.pgs[PART + 1]; ++g) {
        const int mi = PT.grp_m[g] + PP;
        const float4 Em = xb[mi];

        const float2 w12 = shw12[mi];
        const float p0 = Em.x * Em.x + Em.y * Em.y;
        const float p1 = Em.z * Em.z + Em.w * Em.w;
        acc[4] += w12.x * (2.0f * p0 + p1);
        acc[5] += w12.x * (2.0f * p1 + p0);
        const float xrr = Em.x * Em.z + Em.y * Em.w;
        const float xri = Em.y * Em.z - Em.x * Em.w;
        acc[6] += w12.y * xrr;
        acc[7] += w12.y * xri;

        float g0r = 0.f, g0i = 0.f, g1r = 0.f, g1i = 0.f;
#pragma unroll
        for (int h = PT.gpair[g]; h < PT.gpair[g + 1]; ++h) {
            const int nn = PT.npair[h];
            const float4 xn = xb[PP + nn];
            const float4 xs = xb[mi + nn];
            const float Sr = xn.x * xs.x + xn.y * xs.y + xn.z * xs.z + xn.w * xs.w;
            const float Si = xn.y * xs.x - xn.x * xs.y + xn.w * xs.z - xn.z * xs.w;
            const float4 w = shw[h];
            g0r += Sr * w.x - Si * w.y;
            g0i += Sr * w.y + Si * w.x;
            g1r += Sr * w.z - Si * w.w;
            g1i += Sr * w.w + Si * w.z;
        }
        acc[0] += g0r * Em.x - g0i * Em.y;
        acc[1] += g0r * Em.y + g0i * Em.x;
        acc[2] += g1r * Em.z - g1i * Em.w;
        acc[3] += g1r * Em.w + g1i * Em.z;
    }
}

__global__ __launch_bounds__(TPB)
void eqampbc_kernel(const float* __restrict__ x_real,  long long xr_sz,
                    const float* __restrict__ x_imag,  long long xi_sz,
                    const float* __restrict__ task_info, long long ti_sz,
                    const float* __restrict__ C00,     long long c00_sz,
                    const float* __restrict__ fwm_wr,  long long wr_sz,
                    const float* __restrict__ fwm_wi,  long long wi_sz,
                    const float* __restrict__ conv1_w, long long c1_sz,
                    const float* __restrict__ conv2_w, long long c2_sz,
                    float* __restrict__ out,           long long out_floats,
                    int B)
{
    __shared__ float4 shx[NB * MM];   // 41984 B; stride 164 words: conflict-free
    __shared__ float4 shw[HDIM];      //  4160 B; part-major permuted weights
    __shared__ float2 shw12[MM];      //   328 B
    __shared__ float4 pbuf[NB * 2];   //  2048 B; part1 partial sums

    const int tid = threadIdx.x;
    const int b0  = blockIdx.x * NB;

    // ---- stage fwm weights permuted to part-major order ----
    {
        constexpr PTab PT{};
        for (int h = tid; h < HDIM; h += TPB) {
            const int oh = PT.origh[h];
            const float w0r = (oh < wr_sz)        ? fwm_wr[oh]        : 0.0f;
            const float w0i = (oh < wi_sz)        ? fwm_wi[oh]        : 0.0f;
            const float w1r = (HDIM + oh < wr_sz) ? fwm_wr[HDIM + oh] : 0.0f;
            const float w1i = (HDIM + oh < wi_sz) ? fwm_wi[HDIM + oh] : 0.0f;
            shw[h] = make_float4(w0r, w0i, w1r, w1i);
        }
    }
    if (tid < MM) {
        const float w1 = (tid == PP || tid >= c1_sz) ? 0.0f : conv1_w[tid];
        const float w2 = (tid == PP || tid >= c2_sz) ? 0.0f : conv2_w[tid];
        shw12[tid] = make_float2(w1, w2);
    }

    // ---- stage x tile ----
    {
        int rem = B - b0; if (rem > NB) rem = NB;
        int lim = rem * MM;
        const long long base = (long long)b0 * (MM * 2);
        long long mxs = xr_sz < xi_sz ? xr_sz : xi_sz;
        long long avail = (mxs - base) / 2;
        if (avail < 0) avail = 0;
        if ((long long)lim > avail) lim = (int)avail;
        for (int j = tid; j < lim; j += TPB) {
            const long long g = base + (long long)j * 2;
            shx[j] = make_float4(x_real[g], x_imag[g], x_real[g + 1], x_imag[g + 1]);
        }
        for (int j = lim + tid; j < NB * MM; j += TPB)
            shx[j] = make_float4(0.f, 0.f, 0.f, 0.f);
    }
    __syncthreads();

    const int part = tid >> 6;        // warp-uniform (warps 0-1: part0, 2-3: part1)
    const int bl   = tid & 63;        // local batch
    const float4* __restrict__ xb = shx + bl * MM;

    float acc[8] = {0.f, 0.f, 0.f, 0.f, 0.f, 0.f, 0.f, 0.f};
    if (part == 0) fwm_part<0>(xb, shw, shw12, acc);
    else           fwm_part<1>(xb, shw, shw12, acc);

    if (part == 1) {
        pbuf[bl * 2 + 0] = make_float4(acc[0], acc[1], acc[2], acc[3]);
        pbuf[bl * 2 + 1] = make_float4(acc[4], acc[5], acc[6], acc[7]);
    }
    __syncthreads();

    if (part == 0) {
        const float4 u = pbuf[bl * 2 + 0];
        const float4 v = pbuf[bl * 2 + 1];
        const float E0r = acc[0] + u.x, E0i = acc[1] + u.y;
        const float E1r = acc[2] + u.z, E1i = acc[3] + u.w;
        const float ph0 = acc[4] + v.x, ph1 = acc[5] + v.y;
        const float c0r = acc[6] + v.z, c0i = acc[7] + v.w;

        const int b = b0 + bl;
        if (b < B) {
            const float4 xp = xb[PP];
            const long long tix = (long long)b * 4;
            const float ti0 = (tix < ti_sz) ? task_info[tix] : 0.0f;
            const float P   = 0.5f * exp10f(ti0 * 0.1f);
            const float c00 = (c00_sz > 0) ? C00[0] : 0.0f;
            const float pwp = xp.x * xp.x + xp.y * xp.y + xp.z * xp.z + xp.w * xp.w;
            const float phi0 = P * (c00 * pwp + 2.0f * ph0);
            const float phi1 = P * (c00 * pwp + 2.0f * ph1);
            float s0, cs0, s1, cs1;
            sincosf(phi0, &s0, &cs0);
            sincosf(phi1, &s1, &cs1);

            const float t0r = -(xp.z * c0i + xp.w * c0r);
            const float t0i =  (xp.z * c0r - xp.w * c0i);
            const float t1r =  (xp.x * c0i - xp.y * c0r);
            const float t1i =  (xp.x * c0r + xp.y * c0i);

            const float o0 = P * (E0r + t0r) + (xp.x * cs0 - xp.y * s0);  // re(b,0)
            const float o1 = P * (E0i + t0i) + (xp.x * s0 + xp.y * cs0);  // im(b,0)
            const float o2 = P * (E1r + t1r) + (xp.z * cs1 - xp.w * s1);  // re(b,1)
            const float o3 = P * (E1i + t1i) + (xp.z * s1 + xp.w * cs1);  // im(b,1)

            const long long reIdx = 2LL * b;
            const long long imIdx = 2LL * B + 2LL * b;
            if (imIdx + 1 < out_floats) {
                float2* __restrict__ out2 = (float2*)out;
                out2[b]     = make_float2(o0, o2);   // re-block, coalesced
                out2[B + b] = make_float2(o1, o3);   // im-block, coalesced
            } else {
                if (reIdx     < out_floats) out[reIdx]     = o0;
                if (reIdx + 1 < out_floats) out[reIdx + 1] = o2;
                if (imIdx     < out_floats) out[imIdx]     = o1;
                if (imIdx + 1 < out_floats) out[imIdx + 1] = o3;
            }
        }
    }
}

extern "C" void kernel_launch(void* const* d_in, const int* in_sizes, int n_in,
                              void* d_out, int out_size)
{
    if (n_in < 8) return;

    bool has41 = false, has164 = false;
    for (int i = 0; i < n_in; ++i) {
        if (in_sizes[i] == 41)  has41 = true;
        if (in_sizes[i] == 164) has164 = true;
    }
    int div = 1;
    if (has41)       div = 1;
    else if (has164) div = 4;   // byte counts (established)
    else return;

    long long es[64];
    const int ni = n_in < 64 ? n_in : 64;
    long long mx = 0;
    for (int i = 0; i < ni; ++i) {
        es[i] = (long long)in_sizes[i] / div;
        if (es[i] > mx) mx = es[i];
    }
    const long long Bll = mx / (MM * 2);
    if (Bll <= 0 || Bll * (MM * 2) != mx) return;

    int ixr = 0, ixi = 1, iti = 2, ic00 = 3, iwr = 4, iwi = 5, ic1 = 6, ic2 = 7;
    bool pos_ok =
           es[0] == Bll * MM * 2 && es[1] == Bll * MM * 2
        && es[2] == Bll * 4      && es[3] == 1
        && es[4] == 2 * HDIM     && es[5] == 2 * HDIM
        && es[6] == MM           && es[7] == MM;

    if (!pos_ok) {
        ixr = ixi = iti = ic00 = iwr = iwi = ic1 = ic2 = -1;
        for (int i = 0; i < ni; ++i) {
            const long long s = es[i];
            if (s == mx)            { if (ixr < 0) ixr = i; else ixi = i; }
            else if (s == 1)        { ic00 = i; }
            else if (s == 2 * HDIM) { if (iwr < 0) iwr = i; else iwi = i; }
            else if (s == MM)       { if (ic1 < 0) ic1 = i; else ic2 = i; }
            else if (s == Bll * 4)  { iti = i; }
        }
        if (ixr < 0 || ixi < 0 || iti < 0 || ic00 < 0 ||
            iwr < 0 || iwi < 0 || ic1 < 0 || ic2 < 0)
            return;
    }

    const int B = (int)Bll;
    const long long want = (long long)B * 4;
    long long cap = (long long)out_size / div;
    long long out_floats = want < cap ? want : cap;

    const int grid = (B + NB - 1) / NB;
    eqampbc_kernel<<<grid, TPB>>>(
        (const float*)d_in[ixr], es[ixr],
        (const float*)d_in[ixi], es[ixi],
        (const float*)d_in[iti], es[iti],
        (const float*)d_in[ic00], es[ic00],
        (const float*)d_in[iwr], es[iwr],
        (const float*)d_in[iwi], es[iwi],
        (const float*)d_in[ic1], es[ic1],
        (const float*)d_in[ic2], es[ic2],
        (float*)d_out, out_floats, B);
}

// round 17
// speedup vs baseline: 2.1626x; 2.1626x over previous
#include <cuda_runtime.h>
#include <math.h>

// ---------------------------------------------------------------------------
// EqAMPBC: M=41, RHO=1.0, Nmodes=2, B=131072
// PLANAR complex output: out[0..2B)=re (B,2), out[2B..4B)=im (B,2).
// in_sizes / out_size are BYTE counts.
// R17: 2 threads/batch split by mi-range, R15 code shape (monolithic unrolled
// loops, scalar accumulators) to avoid the R16 local-memory spill.
// ---------------------------------------------------------------------------

#define MM    41
#define PP    20
#define HDIM  260
#define NB    64         // batches per block
#define TPB   128        // 2 threads per batch

// Reference-order tables (identical to R15; proven to fold to immediates).
struct Tables {
    short n_of_h[HDIM];
    short h_start[MM + 1];
    int   cnt;
    constexpr Tables() : n_of_h(), h_start(), cnt(0) {
        int idx = 0;
        for (int mi = 0; mi < MM; ++mi) {
            h_start[mi] = (short)idx;
            const int m = mi - PP;
            for (int n = -PP; n <= PP; ++n) {
                int mn = m * n;   if (mn  < 0) mn  = -mn;
                int mpn = m + n;  if (mpn < 0) mpn = -mpn;
                if (m != 0 && n != 0 && mn <= PP && mpn <= PP) {
                    n_of_h[idx] = (short)n;
                    ++idx;
                }
            }
        }
        h_start[MM] = (short)idx;
        cnt = idx;
    }
};
static_assert(Tables().cnt == HDIM, "HDIM mismatch with reference fwm_index");
static_assert(Tables().h_start[PP] == 130, "half split mismatch");      // mi<PP: 130 pairs
static_assert(Tables().h_start[PP + 1] == 130, "PP group must be empty");

// The per-mi body, expanded inline in both part loops (macro keeps one source).
#define FWM_GROUP_BODY(mi_)                                                  \
    {                                                                        \
        const float4 Em = xb[(mi_)];                                         \
        const float2 w12 = shw12[(mi_)];                                     \
        const float p0 = Em.x * Em.x + Em.y * Em.y;                          \
        const float p1 = Em.z * Em.z + Em.w * Em.w;                          \
        ph0 += w12.x * (2.0f * p0 + p1);                                     \
        ph1 += w12.x * (2.0f * p1 + p0);                                     \
        const float xrr = Em.x * Em.z + Em.y * Em.w;                         \
        const float xri = Em.y * Em.z - Em.x * Em.w;                         \
        c0r += w12.y * xrr;                                                  \
        c0i += w12.y * xri;                                                  \
        float g0r = 0.f, g0i = 0.f, g1r = 0.f, g1i = 0.f;                    \
        _Pragma("unroll")                                                    \
        for (int h = TB.h_start[(mi_)]; h < TB.h_start[(mi_) + 1]; ++h) {    \
            const int nn = TB.n_of_h[h];                                     \
            const float4 xn = xb[PP + nn];                                   \
            const float4 xs = xb[(mi_) + nn];                                \
            const float Sr = xn.x * xs.x + xn.y * xs.y + xn.z * xs.z + xn.w * xs.w; \
            const float Si = xn.y * xs.x - xn.x * xs.y + xn.w * xs.z - xn.z * xs.w; \
            const float4 w = shw[h];                                         \
            g0r += Sr * w.x - Si * w.y;                                      \
            g0i += Sr * w.y + Si * w.x;                                      \
            g1r += Sr * w.z - Si * w.w;                                      \
            g1i += Sr * w.w + Si * w.z;                                      \
        }                                                                    \
        E0r += g0r * Em.x - g0i * Em.y;                                      \
        E0i += g0r * Em.y + g0i * Em.x;                                      \
        E1r += g1r * Em.z - g1i * Em.w;                                      \
        E1i += g1r * Em.w + g1i * Em.z;                                      \
    }

__global__ __launch_bounds__(TPB)
void eqampbc_kernel(const float* __restrict__ x_real,  long long xr_sz,
                    const float* __restrict__ x_imag,  long long xi_sz,
                    const float* __restrict__ task_info, long long ti_sz,
                    const float* __restrict__ C00,     long long c00_sz,
                    const float* __restrict__ fwm_wr,  long long wr_sz,
                    const float* __restrict__ fwm_wi,  long long wi_sz,
                    const float* __restrict__ conv1_w, long long c1_sz,
                    const float* __restrict__ conv2_w, long long c2_sz,
                    float* __restrict__ out,           long long out_floats,
                    int B)
{
    __shared__ float4 shx[NB * MM];   // 41984 B; stride 164 words: conflict-free
    __shared__ float4 shw[HDIM];      //  4160 B; reference order (as in R15)
    __shared__ float2 shw12[MM];      //   328 B
    __shared__ float4 pbuf[NB * 2];   //  2048 B; part1 partial sums
    // total 48520 B < 49152 B -> 4 CTAs/SM, 16 warps/SM

    const int tid = threadIdx.x;
    const int b0  = blockIdx.x * NB;

    // ---- stage fwm weights (identical to R15) ----
    for (int h = tid; h < HDIM; h += TPB) {
        const float w0r = (h < wr_sz)        ? fwm_wr[h]        : 0.0f;
        const float w0i = (h < wi_sz)        ? fwm_wi[h]        : 0.0f;
        const float w1r = (HDIM + h < wr_sz) ? fwm_wr[HDIM + h] : 0.0f;
        const float w1i = (HDIM + h < wi_sz) ? fwm_wi[HDIM + h] : 0.0f;
        shw[h] = make_float4(w0r, w0i, w1r, w1i);
    }
    if (tid < MM) {
        const float w1 = (tid == PP || tid >= c1_sz) ? 0.0f : conv1_w[tid];
        const float w2 = (tid == PP || tid >= c2_sz) ? 0.0f : conv2_w[tid];
        shw12[tid] = make_float2(w1, w2);
    }

    // ---- stage x tile ----
    {
        int rem = B - b0; if (rem > NB) rem = NB;
        int lim = rem * MM;
        const long long base = (long long)b0 * (MM * 2);
        long long mxs = xr_sz < xi_sz ? xr_sz : xi_sz;
        long long avail = (mxs - base) / 2;
        if (avail < 0) avail = 0;
        if ((long long)lim > avail) lim = (int)avail;
        for (int j = tid; j < lim; j += TPB) {
            const long long g = base + (long long)j * 2;
            shx[j] = make_float4(x_real[g], x_imag[g], x_real[g + 1], x_imag[g + 1]);
        }
        for (int j = lim + tid; j < NB * MM; j += TPB)
            shx[j] = make_float4(0.f, 0.f, 0.f, 0.f);
    }
    __syncthreads();

    const int part = tid >> 6;        // warps 0-1: part0 (mi>PP), warps 2-3: part1
    const int bl   = tid & 63;
    const float4* __restrict__ xb = shx + bl * MM;
    constexpr Tables TB{};

    float E0r = 0.f, E0i = 0.f, E1r = 0.f, E1i = 0.f;
    float ph0 = 0.f, ph1 = 0.f;
    float c0r = 0.f, c0i = 0.f;

    if (part == 0) {
#pragma unroll
        for (int mi = PP + 1; mi < MM; ++mi)
            FWM_GROUP_BODY(mi)
    } else {
#pragma unroll
        for (int mi = 0; mi < PP; ++mi)
            FWM_GROUP_BODY(mi)
    }

    if (part == 1) {
        pbuf[bl * 2 + 0] = make_float4(E0r, E0i, E1r, E1i);
        pbuf[bl * 2 + 1] = make_float4(ph0, ph1, c0r, c0i);
    }
    __syncthreads();

    if (part == 0) {
        const float4 u = pbuf[bl * 2 + 0];
        const float4 v = pbuf[bl * 2 + 1];
        E0r += u.x; E0i += u.y; E1r += u.z; E1i += u.w;
        ph0 += v.x; ph1 += v.y; c0r += v.z; c0i += v.w;

        const int b = b0 + bl;
        if (b < B) {
            const float4 xp = xb[PP];
            const long long tix = (long long)b * 4;
            const float ti0 = (tix < ti_sz) ? task_info[tix] : 0.0f;
            const float P   = 0.5f * exp10f(ti0 * 0.1f);
            const float c00 = (c00_sz > 0) ? C00[0] : 0.0f;
            const float pwp = xp.x * xp.x + xp.y * xp.y + xp.z * xp.z + xp.w * xp.w;
            const float phi0 = P * (c00 * pwp + 2.0f * ph0);
            const float phi1 = P * (c00 * pwp + 2.0f * ph1);
            float s0, cs0, s1, cs1;
            sincosf(phi0, &s0, &cs0);
            sincosf(phi1, &s1, &cs1);

            const float t0r = -(xp.z * c0i + xp.w * c0r);
            const float t0i =  (xp.z * c0r - xp.w * c0i);
            const float t1r =  (xp.x * c0i - xp.y * c0r);
            const float t1i =  (xp.x * c0r + xp.y * c0i);

            const float o0 = P * (E0r + t0r) + (xp.x * cs0 - xp.y * s0);  // re(b,0)
            const float o1 = P * (E0i + t0i) + (xp.x * s0 + xp.y * cs0);  // im(b,0)
            const float o2 = P * (E1r + t1r) + (xp.z * cs1 - xp.w * s1);  // re(b,1)
            const float o3 = P * (E1i + t1i) + (xp.z * s1 + xp.w * cs1);  // im(b,1)

            const long long reIdx = 2LL * b;
            const long long imIdx = 2LL * B + 2LL * b;
            if (imIdx + 1 < out_floats) {
                float2* __restrict__ out2 = (float2*)out;
                out2[b]     = make_float2(o0, o2);   // re-block, coalesced
                out2[B + b] = make_float2(o1, o3);   // im-block, coalesced
            } else {
                if (reIdx     < out_floats) out[reIdx]     = o0;
                if (reIdx + 1 < out_floats) out[reIdx + 1] = o2;
                if (imIdx     < out_floats) out[imIdx]     = o1;
                if (imIdx + 1 < out_floats) out[imIdx + 1] = o3;
            }
        }
    }
}

extern "C" void kernel_launch(void* const* d_in, const int* in_sizes, int n_in,
                              void* d_out, int out_size)
{
    if (n_in < 8) return;

    bool has41 = false, has164 = false;
    for (int i = 0; i < n_in; ++i) {
        if (in_sizes[i] == 41)  has41 = true;
        if (in_sizes[i] == 164) has164 = true;
    }
    int div = 1;
    if (has41)       div = 1;
    else if (has164) div = 4;   // byte counts (established)
    else return;

    long long es[64];
    const int ni = n_in < 64 ? n_in : 64;
    long long mx = 0;
    for (int i = 0; i < ni; ++i) {
        es[i] = (long long)in_sizes[i] / div;
        if (es[i] > mx) mx = es[i];
    }
    const long long Bll = mx / (MM * 2);
    if (Bll <= 0 || Bll * (MM * 2) != mx) return;

    int ixr = 0, ixi = 1, iti = 2, ic00 = 3, iwr = 4, iwi = 5, ic1 = 6, ic2 = 7;
    bool pos_ok =
           es[0] == Bll * MM * 2 && es[1] == Bll * MM * 2
        && es[2] == Bll * 4      && es[3] == 1
        && es[4] == 2 * HDIM     && es[5] == 2 * HDIM
        && es[6] == MM           && es[7] == MM;

    if (!pos_ok) {
        ixr = ixi = iti = ic00 = iwr = iwi = ic1 = ic2 = -1;
        for (int i = 0; i < ni; ++i) {
            const long long s = es[i];
            if (s == mx)            { if (ixr < 0) ixr = i; else ixi = i; }
            else if (s == 1)        { ic00 = i; }
            else if (s == 2 * HDIM) { if (iwr < 0) iwr = i; else iwi = i; }
            else if (s == MM)       { if (ic1 < 0) ic1 = i; else ic2 = i; }
            else if (s == Bll * 4)  { iti = i; }
        }
        if (ixr < 0 || ixi < 0 || iti < 0 || ic00 < 0 ||
            iwr < 0 || iwi < 0 || ic1 < 0 || ic2 < 0)
            return;
    }

    const int B = (int)Bll;
    const long long want = (long long)B * 4;
    long long cap = (long long)out_size / div;
    long long out_floats = want < cap ? want : cap;

    const int grid = (B + NB - 1) / NB;
    eqampbc_kernel<<<grid, TPB>>>(
        (const float*)d_in[ixr], es[ixr],
        (const float*)d_in[ixi], es[ixi],
        (const float*)d_in[iti], es[iti],
        (const float*)d_in[ic00], es[ic00],
        (const float*)d_in[iwr], es[iwr],
        (const float*)d_in[iwi], es[iwi],
        (const float*)d_in[ic1], es[ic1],
        (const float*)d_in[ic2], es[ic2],
        (float*)d_out, out_floats, B);
}